// round 2
// baseline (speedup 1.0000x reference)
#include <cuda_runtime.h>
#include <math.h>

// Problem constants (from reference): B=2048 (derived), S=200, H=128, F=4H=512, NH=4
#define S_DIM 200
#define H_DIM 128
#define F_DIM 512
#define NH_DIM 4
#define FT 128            // W1 f-tile width
#define NFT (F_DIM / FT)  // 4 tiles
#define XP 210            // xpt row pitch (floats): even (8B align), 210%32=18 -> <=2-way conflicts
#define ATTP 208
#define NTHREADS 320
#define SPT 10            // s rows per thread (20 groups * 10 = 200, no padding waste)
#define FPT 8             // f cols per thread (16 groups * 8 = 128 = FT)

typedef unsigned long long u64;

// ---- packed f32x2 helpers (FFMA2: 2x fp32 FMA throughput on sm_103a) ----
__device__ __forceinline__ u64 dup2(float x) {
    u64 r; asm("mov.b64 %0, {%1,%1};" : "=l"(r) : "f"(x)); return r;
}
__device__ __forceinline__ void unpack2(u64 v, float& x, float& y) {
    asm("mov.b64 {%0,%1}, %2;" : "=f"(x), "=f"(y) : "l"(v));
}
__device__ __forceinline__ void ffma2(u64& d, u64 a, u64 b) {
    asm("fma.rn.f32x2 %0, %1, %2, %0;" : "+l"(d) : "l"(a), "l"(b));
}

__global__ __launch_bounds__(NTHREADS, 1)
void mha_fused_kernel(const float* __restrict__ item,
                      const int*   __restrict__ mask,
                      const float* __restrict__ pos,
                      const float* __restrict__ W1,
                      const float* __restrict__ W2,
                      float* __restrict__ out)
{
    extern __shared__ float sm[];
    float* xpt  = sm;                       // [H_DIM][XP]   x_pos transposed: xpt[h*XP + s]
    float* w1s  = xpt + H_DIM * XP;         // [H_DIM][FT]   current W1 tile
    float* w2s  = w1s + H_DIM * FT;         // [F_DIM][NH]
    float* atts = w2s + F_DIM * NH_DIM;     // [NH][ATTP]    att logits -> softmax weights

    const int tid = threadIdx.x;
    const int b   = blockIdx.x;
    const int sg  = tid >> 4;   // 0..19 : owns s rows [sg*10, sg*10+10)
    const int fq  = tid & 15;   // 0..15 : owns f cols [fq*8, fq*8+8) within tile

    // ---- Phase 0: load x_pos (transposed) and W2 into smem ----
    const float* itemb = item + (size_t)b * (S_DIM * H_DIM);
    for (int idx = tid; idx < S_DIM * H_DIM; idx += NTHREADS) {
        int s = idx >> 7;       // idx / 128
        int h = idx & 127;
        xpt[h * XP + s] = itemb[idx] + pos[idx];   // pos is [S,H], same linear idx
    }
    for (int idx = tid; idx < F_DIM * NH_DIM; idx += NTHREADS)
        w2s[idx] = W2[idx];

    // per-thread att-logit partials over its 10 s rows (summed over this thread's f cols)
    float attacc[SPT][NH_DIM];
    #pragma unroll
    for (int i = 0; i < SPT; i++)
        #pragma unroll
        for (int k = 0; k < NH_DIM; k++) attacc[i][k] = 0.0f;

    // ---- Phase 1: hidden = tanh(x_pos @ W1) fused with att += hidden @ W2 ----
    for (int ft = 0; ft < NFT; ft++) {
        __syncthreads();   // previous tile compute done (and xpt ready on first iter)
        for (int idx = tid; idx < H_DIM * FT; idx += NTHREADS) {
            int r = idx >> 7;      // k index (0..127)
            int c = idx & 127;     // f within tile
            w1s[idx] = W1[r * F_DIM + ft * FT + c];
        }
        __syncthreads();

        u64 acc[5][8];             // 5 s-pairs x 8 f, packed fp32x2 over s
        #pragma unroll
        for (int i = 0; i < 5; i++)
            #pragma unroll
            for (int j = 0; j < 8; j++) acc[i][j] = 0ull;

        const float* xbase = xpt + sg * SPT;
        const float* bbase = w1s + fq * FPT;

        #pragma unroll 2
        for (int k = 0; k < H_DIM; k++) {
            const u64* ap = (const u64*)(xbase + k * XP);   // 8B aligned: (210k+10sg)*4 % 8 == 0
            u64 a0 = ap[0], a1 = ap[1], a2 = ap[2], a3 = ap[3], a4 = ap[4];
            const float4* bp = (const float4*)(bbase + k * FT);
            float4 b0 = bp[0], b1 = bp[1];
            u64 B0 = dup2(b0.x), B1 = dup2(b0.y), B2 = dup2(b0.z), B3 = dup2(b0.w);
            u64 B4 = dup2(b1.x), B5 = dup2(b1.y), B6 = dup2(b1.z), B7 = dup2(b1.w);
            #pragma unroll
            for (int j = 0; j < 8; j++) {
                u64 Bj = (j==0)?B0:(j==1)?B1:(j==2)?B2:(j==3)?B3:(j==4)?B4:(j==5)?B5:(j==6)?B6:B7;
                ffma2(acc[0][j], a0, Bj);
                ffma2(acc[1][j], a1, Bj);
                ffma2(acc[2][j], a2, Bj);
                ffma2(acc[3][j], a3, Bj);
                ffma2(acc[4][j], a4, Bj);
            }
        }

        // epilogue: tanh + contract with W2 into att partials
        #pragma unroll
        for (int j = 0; j < 8; j++) {
            int f = ft * FT + fq * FPT + j;
            float w0 = w2s[f * 4 + 0], w1v = w2s[f * 4 + 1];
            float w2v = w2s[f * 4 + 2], w3v = w2s[f * 4 + 3];
            #pragma unroll
            for (int i = 0; i < 5; i++) {
                float h0, h1; unpack2(acc[i][j], h0, h1);
                h0 = tanhf(h0); h1 = tanhf(h1);
                attacc[2*i  ][0] += h0 * w0;  attacc[2*i  ][1] += h0 * w1v;
                attacc[2*i  ][2] += h0 * w2v; attacc[2*i  ][3] += h0 * w3v;
                attacc[2*i+1][0] += h1 * w0;  attacc[2*i+1][1] += h1 * w1v;
                attacc[2*i+1][2] += h1 * w2v; attacc[2*i+1][3] += h1 * w3v;
            }
        }
    }

    // ---- Phase 2: reduce att partials across the 16 f-lanes (fq = lane&15) ----
    #pragma unroll
    for (int i = 0; i < SPT; i++) {
        #pragma unroll
        for (int k = 0; k < NH_DIM; k++) {
            float v = attacc[i][k];
            v += __shfl_xor_sync(0xffffffffu, v, 1);
            v += __shfl_xor_sync(0xffffffffu, v, 2);
            v += __shfl_xor_sync(0xffffffffu, v, 4);
            v += __shfl_xor_sync(0xffffffffu, v, 8);
            if (fq == 0) atts[k * ATTP + sg * SPT + i] = v;
        }
    }
    __syncthreads();

    // ---- Phase 3: mask + softmax (one warp per head) ----
    if (tid < 32 * NH_DIM) {
        const int k = tid >> 5;
        const int lane = tid & 31;
        const int* mrow = mask + (size_t)b * S_DIM;
        const float NEGV = -4294967296.0f;   // float32(-2^32+1)
        float mx = -INFINITY;
        for (int s = lane; s < S_DIM; s += 32) {
            float v = atts[k * ATTP + s];
            if (mrow[s] == 0) v = NEGV;
            atts[k * ATTP + s] = v;
            mx = fmaxf(mx, v);
        }
        #pragma unroll
        for (int o = 16; o > 0; o >>= 1) mx = fmaxf(mx, __shfl_xor_sync(0xffffffffu, mx, o));
        float sum = 0.0f;
        for (int s = lane; s < S_DIM; s += 32) {
            float e = expf(atts[k * ATTP + s] - mx);
            atts[k * ATTP + s] = e;
            sum += e;
        }
        #pragma unroll
        for (int o = 16; o > 0; o >>= 1) sum += __shfl_xor_sync(0xffffffffu, sum, o);
        float inv = 1.0f / sum;
        for (int s = lane; s < S_DIM; s += 32) atts[k * ATTP + s] *= inv;
    }
    __syncthreads();

    // ---- Phase 4: interest[k][h] = sum_s att[k][s] * (x_pos[s][h] - pos[s][h]) ----
    if (tid < H_DIM) {
        const int h = tid;
        const float* xr = xpt + h * XP;
        const float* pc = pos + h;
        float a0 = 0.f, a1 = 0.f, a2 = 0.f, a3 = 0.f;
        #pragma unroll 4
        for (int s = 0; s < S_DIM; s++) {
            float xv = xr[s] - pc[(size_t)s * H_DIM];
            float t0 = atts[0 * ATTP + s], t1 = atts[1 * ATTP + s];
            float t2 = atts[2 * ATTP + s], t3 = atts[3 * ATTP + s];
            a0 += t0 * xv; a1 += t1 * xv; a2 += t2 * xv; a3 += t3 * xv;
        }
        float* ob = out + (size_t)b * (NH_DIM * H_DIM);
        ob[0 * H_DIM + h] = a0;
        ob[1 * H_DIM + h] = a1;
        ob[2 * H_DIM + h] = a2;
        ob[3 * H_DIM + h] = a3;
    }
}

extern "C" void kernel_launch(void* const* d_in, const int* in_sizes, int n_in,
                              void* d_out, int out_size)
{
    const float* item = (const float*)d_in[0];   // [B,S,H] f32
    const int*   mask = (const int*)  d_in[1];   // [B,S]   i32
    const float* pos  = (const float*)d_in[2];   // [1,S,H] f32
    const float* W1   = (const float*)d_in[3];   // [H,4H]  f32
    const float* W2   = (const float*)d_in[4];   // [4H,NH] f32
    float* out = (float*)d_out;                  // [B,NH,H] f32

    const int B = in_sizes[0] / (S_DIM * H_DIM);
    const size_t smem = (size_t)(H_DIM * XP + H_DIM * FT + F_DIM * NH_DIM + NH_DIM * ATTP) * sizeof(float);

    cudaFuncSetAttribute(mha_fused_kernel,
                         cudaFuncAttributeMaxDynamicSharedMemorySize, (int)smem);
    mha_fused_kernel<<<B, NTHREADS, smem>>>(item, mask, pos, W1, W2, out);
}

// round 4
// speedup vs baseline: 2.0104x; 2.0104x over previous
#include <cuda_runtime.h>
#include <math.h>
#include <stdint.h>

#define S_DIM 200
#define H_DIM 128
#define F_DIM 512
#define NH 4
#define ATTP 208
#define NT 256

// smem layout (bytes). xw region is reused: first X (224*132*4=118272 B),
// then the permuted W1 half fragment buffer (512 blocks * 72 words * 4 = 147456 B).
#define SM_XW    0
#define XW_BYTES 147456
#define SM_W2    XW_BYTES
#define SM_ATT   (SM_W2 + 8192)
#define SM_OUTB  (SM_ATT + 3328)
#define SM_TOTAL (SM_OUTB + 2048)   // 161024 B

static __device__ __forceinline__ uint32_t smem_u32(const void* p) {
    uint32_t a;
    asm("{ .reg .u64 t; cvta.to.shared.u64 t, %1; cvt.u32.u64 %0, t; }" : "=r"(a) : "l"(p));
    return a;
}
static __device__ __forceinline__ uint32_t f2tf32(float x) {
    uint32_t r; asm("cvt.rna.tf32.f32 %0, %1;" : "=r"(r) : "f"(x)); return r;
}
static __device__ __forceinline__ float fast_tanh(float x) {
    // tanh(x) = 1 - 2/(exp(2x)+1); exact limits at +-inf, ~1e-6 rel err
    float y = x * 2.8853900817779268f;   // 2*log2(e)
    float t; asm("ex2.approx.f32 %0, %1;" : "=f"(t) : "f"(y));
    float r; asm("rcp.approx.f32 %0, %1;" : "=f"(r) : "f"(t + 1.0f));
    return fmaf(-2.0f, r, 1.0f);
}
static __device__ __forceinline__ void mma_tf32(float* c, const uint32_t* a,
                                                uint32_t b0, uint32_t b1) {
    asm volatile(
        "mma.sync.aligned.m16n8k8.row.col.f32.tf32.tf32.f32 "
        "{%0,%1,%2,%3}, {%4,%5,%6,%7}, {%8,%9}, {%0,%1,%2,%3};"
        : "+f"(c[0]), "+f"(c[1]), "+f"(c[2]), "+f"(c[3])
        : "r"(a[0]), "r"(a[1]), "r"(a[2]), "r"(a[3]), "r"(b0), "r"(b1));
}

__global__ __launch_bounds__(NT, 1)
void mha_mma_kernel(const float* __restrict__ item,
                    const int*   __restrict__ mask,
                    const float* __restrict__ pos,
                    const float* __restrict__ W1,
                    const float* __restrict__ W2,
                    float* __restrict__ out)
{
    extern __shared__ char smem[];
    const uint32_t smb = smem_u32(smem);
    uint32_t* xw32 = (uint32_t*)(smem + SM_XW);
    float*    w2s  = (float*)(smem + SM_W2);
    float*    atts = (float*)(smem + SM_ATT);
    float*    outb = (float*)(smem + SM_OUTB);

    const int tid = threadIdx.x, wid = tid >> 5, lane = tid & 31;
    const int g = lane >> 2, t = lane & 3;
    const int b = blockIdx.x;
    const float* itemb = item + (size_t)b * (S_DIM * H_DIM);

    // ---- Phase 0: X+pos -> smem (tf32), pitch 132; rows 200..223 zero. W2 copy. ----
    for (int idx = tid; idx < 224 * 128; idx += NT) {
        int row = idx >> 7, h = idx & 127;
        float v = 0.0f;
        if (row < S_DIM) v = itemb[row * 128 + h] + pos[row * 128 + h];
        xw32[row * 132 + h] = f2tf32(v);
    }
    for (int i = tid; i < F_DIM; i += NT)
        ((float4*)w2s)[i] = ((const float4*)W2)[i];
    __syncthreads();

    // ---- Phase 1: hoist A fragments (warp w -> rows 32w..32w+31, 2 M-tiles) ----
    uint32_t A[2][16][4];
    if (wid < 7) {
        #pragma unroll
        for (int mt = 0; mt < 2; mt++) {
            int r0 = wid * 32 + mt * 16 + g;
            #pragma unroll
            for (int kf = 0; kf < 16; kf++) {
                int c0 = kf * 8 + t;
                A[mt][kf][0] = xw32[r0 * 132 + c0];
                A[mt][kf][1] = xw32[(r0 + 8) * 132 + c0];
                A[mt][kf][2] = xw32[r0 * 132 + c0 + 4];
                A[mt][kf][3] = xw32[(r0 + 8) * 132 + c0 + 4];
            }
        }
    }

    float att[2][2][4];
    #pragma unroll
    for (int mt = 0; mt < 2; mt++)
        #pragma unroll
        for (int rh = 0; rh < 2; rh++)
            #pragma unroll
            for (int k = 0; k < 4; k++) att[mt][rh][k] = 0.0f;

    // ---- Phase 2: two W1 halves; per half: stage fragment buffer, then MMA sweep ----
    for (int half = 0; half < 2; half++) {
        __syncthreads();   // A-frag hoist done / previous half's B reads done

        // stage W1[:, half*256 : half*256+256] in fragment order:
        // block blk = nf*16+kf (72-word blocks); lane stores {W1[kf*8+t][col], W1[kf*8+t+4][col]}
        {
            const float* w1h = W1 + half * 256;
            #pragma unroll 1
            for (int i = 0; i < 64; i += 4) {
                float v[8]; uint32_t dst[4];
                #pragma unroll
                for (int j = 0; j < 4; j++) {
                    int blk = wid + (i + j) * 8;
                    int nf = blk >> 4, kf = blk & 15;
                    const float* p0 = w1h + (size_t)(kf * 8 + t) * F_DIM + nf * 8 + g;
                    v[2 * j]     = p0[0];
                    v[2 * j + 1] = p0[4 * F_DIM];
                    dst[j] = smb + SM_XW + blk * 288 + lane * 8;
                }
                #pragma unroll
                for (int j = 0; j < 4; j++) {
                    uint32_t q0 = f2tf32(v[2 * j]), q1 = f2tf32(v[2 * j + 1]);
                    asm volatile("st.shared.v2.b32 [%0], {%1,%2};"
                                 :: "r"(dst[j]), "r"(q0), "r"(q1));
                }
            }
        }
        __syncthreads();

        if (wid < 7) {
            #pragma unroll 1
            for (int np = 0; np < 16; np++) {
                float acc[2][2][4];
                #pragma unroll
                for (int mt = 0; mt < 2; mt++)
                    #pragma unroll
                    for (int nf = 0; nf < 2; nf++)
                        #pragma unroll
                        for (int i = 0; i < 4; i++) acc[mt][nf][i] = 0.0f;

                uint32_t base = smb + SM_XW + np * (32 * 288) + lane * 8;
                #pragma unroll
                for (int kf = 0; kf < 16; kf++) {
                    uint32_t b00, b01, b10, b11;
                    asm volatile("ld.shared.v2.b32 {%0,%1}, [%2];"
                                 : "=r"(b00), "=r"(b01) : "r"(base + kf * 288));
                    asm volatile("ld.shared.v2.b32 {%0,%1}, [%2];"
                                 : "=r"(b10), "=r"(b11) : "r"(base + kf * 288 + 16 * 288));
                    mma_tf32(acc[0][0], A[0][kf], b00, b01);
                    mma_tf32(acc[0][1], A[0][kf], b10, b11);
                    mma_tf32(acc[1][0], A[1][kf], b00, b01);
                    mma_tf32(acc[1][1], A[1][kf], b10, b11);
                }
                // fused epilogue: tanh + W2 contraction into register att partials
                #pragma unroll
                for (int nf = 0; nf < 2; nf++) {
                    int col0 = half * 256 + (np * 2 + nf) * 8 + 2 * t;
                    float4 wA = ((float4*)w2s)[col0];
                    float4 wB = ((float4*)w2s)[col0 + 1];
                    #pragma unroll
                    for (int mt = 0; mt < 2; mt++) {
                        #pragma unroll
                        for (int rh = 0; rh < 2; rh++) {
                            float h0 = fast_tanh(acc[mt][nf][rh * 2 + 0]);  // col 2t
                            float h1 = fast_tanh(acc[mt][nf][rh * 2 + 1]);  // col 2t+1
                            att[mt][rh][0] += h0 * wA.x + h1 * wB.x;
                            att[mt][rh][1] += h0 * wA.y + h1 * wB.y;
                            att[mt][rh][2] += h0 * wA.z + h1 * wB.z;
                            att[mt][rh][3] += h0 * wA.w + h1 * wB.w;
                        }
                    }
                }
            }
        }
    }
    __syncthreads();

    // ---- Phase 3: reduce att over the 4-lane k-group, write atts ----
    if (wid < 7) {
        #pragma unroll
        for (int mt = 0; mt < 2; mt++)
            #pragma unroll
            for (int rh = 0; rh < 2; rh++)
                #pragma unroll
                for (int k = 0; k < 4; k++) {
                    float v = att[mt][rh][k];
                    v += __shfl_xor_sync(0xffffffffu, v, 1);
                    v += __shfl_xor_sync(0xffffffffu, v, 2);
                    if (t == 0) {
                        int s = wid * 32 + mt * 16 + rh * 8 + g;
                        if (s < S_DIM) atts[k * ATTP + s] = v;
                    }
                }
    }
    __syncthreads();

    // ---- Phase 4: mask + softmax (one warp per head) ----
    if (tid < 32 * NH) {
        const int k = tid >> 5, l = tid & 31;
        const int* mrow = mask + (size_t)b * S_DIM;
        const float NEGV = -4294967296.0f;
        float mx = -INFINITY;
        for (int s = l; s < S_DIM; s += 32) {
            float v = atts[k * ATTP + s];
            if (mrow[s] == 0) v = NEGV;
            atts[k * ATTP + s] = v;
            mx = fmaxf(mx, v);
        }
        #pragma unroll
        for (int o = 16; o > 0; o >>= 1) mx = fmaxf(mx, __shfl_xor_sync(0xffffffffu, mx, o));
        float sum = 0.0f;
        for (int s = l; s < S_DIM; s += 32) {
            float e = expf(atts[k * ATTP + s] - mx);
            atts[k * ATTP + s] = e;
            sum += e;
        }
        #pragma unroll
        for (int o = 16; o > 0; o >>= 1) sum += __shfl_xor_sync(0xffffffffu, sum, o);
        float inv = 1.0f / sum;
        for (int s = l; s < S_DIM; s += 32) atts[k * ATTP + s] *= inv;
    }
    __syncthreads();

    // ---- Phase 5: interest[k][h] = sum_s att[k][s] * item[b][s][h] ----
    {
        const int half = tid >> 7, h = tid & 127;
        const float* ib = itemb + h;
        float a0 = 0.f, a1 = 0.f, a2 = 0.f, a3 = 0.f;
        const int s0 = half * 100, s1 = s0 + 100;
        #pragma unroll 4
        for (int s = s0; s < s1; s++) {
            float xv = ib[(size_t)s * H_DIM];
            a0 += atts[0 * ATTP + s] * xv;
            a1 += atts[1 * ATTP + s] * xv;
            a2 += atts[2 * ATTP + s] * xv;
            a3 += atts[3 * ATTP + s] * xv;
        }
        if (half == 1) {
            outb[0 * 128 + h] = a0; outb[1 * 128 + h] = a1;
            outb[2 * 128 + h] = a2; outb[3 * 128 + h] = a3;
        }
        __syncthreads();
        if (half == 0) {
            float* ob = out + (size_t)b * (NH * H_DIM);
            ob[0 * H_DIM + h] = a0 + outb[0 * 128 + h];
            ob[1 * H_DIM + h] = a1 + outb[1 * 128 + h];
            ob[2 * H_DIM + h] = a2 + outb[2 * 128 + h];
            ob[3 * H_DIM + h] = a3 + outb[3 * 128 + h];
        }
    }
}

extern "C" void kernel_launch(void* const* d_in, const int* in_sizes, int n_in,
                              void* d_out, int out_size)
{
    const float* item = (const float*)d_in[0];
    const int*   mask = (const int*)  d_in[1];
    const float* pos  = (const float*)d_in[2];
    const float* W1   = (const float*)d_in[3];
    const float* W2   = (const float*)d_in[4];
    float* out = (float*)d_out;

    const int B = in_sizes[0] / (S_DIM * H_DIM);

    cudaFuncSetAttribute(mha_mma_kernel,
                         cudaFuncAttributeMaxDynamicSharedMemorySize, SM_TOTAL);
    mha_mma_kernel<<<B, NT, SM_TOTAL>>>(item, mask, pos, W1, W2, out);
}

// round 5
// speedup vs baseline: 2.4914x; 1.2393x over previous
#include <cuda_runtime.h>
#include <math.h>
#include <stdint.h>

#define S_DIM 200
#define H_DIM 128
#define F_DIM 512
#define NH 4
#define ATTP 208
#define NT 512
#define MROWS 208          // 13 mtiles of 16 rows
#define NWARP_C 13         // compute warps

// smem layout (bytes). XW region reused: X (208*132*4=109824 B) then
// W1 half fragment buffer (512 blocks * 72 words * 4 = 147456 B).
#define SM_XW    0
#define XW_BYTES 147456
#define SM_W2    XW_BYTES
#define SM_ATT   (SM_W2 + 8192)
#define SM_OUTB  (SM_ATT + 3328)
#define SM_TOTAL (SM_OUTB + 6144)   // 165120 B

static __device__ __forceinline__ uint32_t smem_u32(const void* p) {
    uint32_t a;
    asm("{ .reg .u64 t; cvta.to.shared.u64 t, %1; cvt.u32.u64 %0, t; }" : "=r"(a) : "l"(p));
    return a;
}
static __device__ __forceinline__ uint32_t f2tf32(float x) {
    uint32_t r; asm("cvt.rna.tf32.f32 %0, %1;" : "=r"(r) : "f"(x)); return r;
}
static __device__ __forceinline__ float fast_tanh(float x) {
    // tanh(x) = 1 - 2/(exp(2x)+1); exact limits at +-inf, ~1e-6 rel err
    float y = x * 2.8853900817779268f;   // 2*log2(e)
    float t; asm("ex2.approx.f32 %0, %1;" : "=f"(t) : "f"(y));
    float r; asm("rcp.approx.f32 %0, %1;" : "=f"(r) : "f"(t + 1.0f));
    return fmaf(-2.0f, r, 1.0f);
}
static __device__ __forceinline__ void mma_tf32(float* c, const uint32_t* a,
                                                uint32_t b0, uint32_t b1) {
    asm volatile(
        "mma.sync.aligned.m16n8k8.row.col.f32.tf32.tf32.f32 "
        "{%0,%1,%2,%3}, {%4,%5,%6,%7}, {%8,%9}, {%0,%1,%2,%3};"
        : "+f"(c[0]), "+f"(c[1]), "+f"(c[2]), "+f"(c[3])
        : "r"(a[0]), "r"(a[1]), "r"(a[2]), "r"(a[3]), "r"(b0), "r"(b1));
}

__global__ __launch_bounds__(NT, 1)
void mha_mma_kernel(const float* __restrict__ item,
                    const int*   __restrict__ mask,
                    const float* __restrict__ pos,
                    const float* __restrict__ W1,
                    const float* __restrict__ W2,
                    float* __restrict__ out)
{
    extern __shared__ char smem[];
    const uint32_t smb = smem_u32(smem);
    uint32_t* xw32 = (uint32_t*)(smem + SM_XW);
    float*    w2s  = (float*)(smem + SM_W2);
    float*    atts = (float*)(smem + SM_ATT);
    float*    outb = (float*)(smem + SM_OUTB);

    const int tid = threadIdx.x, wid = tid >> 5, lane = tid & 31;
    const int g = lane >> 2, t = lane & 3;
    const int b = blockIdx.x;
    const float* itemb = item + (size_t)b * (S_DIM * H_DIM);

    // ---- Phase 0: X+pos -> smem (tf32), pitch 132; rows 200..207 zero. W2 copy. ----
    for (int idx = tid; idx < MROWS * 128; idx += NT) {
        int row = idx >> 7, h = idx & 127;
        float v = 0.0f;
        if (row < S_DIM) v = itemb[row * 128 + h] + pos[row * 128 + h];
        xw32[row * 132 + h] = f2tf32(v);
    }
    if (tid < F_DIM) ((float4*)w2s)[tid] = ((const float4*)W2)[tid];
    __syncthreads();

    // ---- Phase 1: hoist A fragments (warp w -> rows 16w..16w+15, 1 M-tile) ----
    uint32_t A[16][4];
    if (wid < NWARP_C) {
        int r0 = wid * 16 + g;
        #pragma unroll
        for (int kf = 0; kf < 16; kf++) {
            int c0 = kf * 8 + t;
            A[kf][0] = xw32[r0 * 132 + c0];
            A[kf][1] = xw32[(r0 + 8) * 132 + c0];
            A[kf][2] = xw32[r0 * 132 + c0 + 4];
            A[kf][3] = xw32[(r0 + 8) * 132 + c0 + 4];
        }
    }

    float att[2][4];
    #pragma unroll
    for (int rh = 0; rh < 2; rh++)
        #pragma unroll
        for (int k = 0; k < 4; k++) att[rh][k] = 0.0f;

    // ---- Phase 2: two W1 halves; per half: stage fragment buffer, then MMA sweep ----
    for (int half = 0; half < 2; half++) {
        __syncthreads();   // A-frag hoist done / previous half's B reads done

        // stage W1[:, half*256 : +256] in fragment order:
        // block blk = nf*16+kf (72-word blocks); lane stores {W1[kf*8+t][col], W1[kf*8+t+4][col]}
        {
            const float* w1h = W1 + half * 256;
            #pragma unroll 1
            for (int i = 0; i < 32; i += 4) {
                float v[8]; uint32_t dst[4];
                #pragma unroll
                for (int j = 0; j < 4; j++) {
                    int blk = wid + (i + j) * 16;
                    int nf = blk >> 4, kf = blk & 15;
                    const float* p0 = w1h + (size_t)(kf * 8 + t) * F_DIM + nf * 8 + g;
                    v[2 * j]     = p0[0];
                    v[2 * j + 1] = p0[4 * F_DIM];
                    dst[j] = smb + SM_XW + blk * 288 + lane * 8;
                }
                #pragma unroll
                for (int j = 0; j < 4; j++) {
                    uint32_t q0 = f2tf32(v[2 * j]), q1 = f2tf32(v[2 * j + 1]);
                    asm volatile("st.shared.v2.b32 [%0], {%1,%2};"
                                 :: "r"(dst[j]), "r"(q0), "r"(q1));
                }
            }
        }
        __syncthreads();

        if (wid < NWARP_C) {
            #pragma unroll 1
            for (int npp = 0; npp < 8; npp++) {    // np-pair: covers 32 N-cols
                float acc[2][2][4];
                #pragma unroll
                for (int p = 0; p < 2; p++)
                    #pragma unroll
                    for (int nf = 0; nf < 2; nf++)
                        #pragma unroll
                        for (int i = 0; i < 4; i++) acc[p][nf][i] = 0.0f;

                uint32_t base = smb + SM_XW + npp * (64 * 288) + lane * 8;
                #pragma unroll
                for (int kf = 0; kf < 16; kf++) {
                    uint32_t b00, b01, b10, b11, b20, b21, b30, b31;
                    uint32_t a0 = base + kf * 288;
                    asm volatile("ld.shared.v2.b32 {%0,%1}, [%2];"
                                 : "=r"(b00), "=r"(b01) : "r"(a0));
                    asm volatile("ld.shared.v2.b32 {%0,%1}, [%2];"
                                 : "=r"(b10), "=r"(b11) : "r"(a0 + 16 * 288));
                    asm volatile("ld.shared.v2.b32 {%0,%1}, [%2];"
                                 : "=r"(b20), "=r"(b21) : "r"(a0 + 32 * 288));
                    asm volatile("ld.shared.v2.b32 {%0,%1}, [%2];"
                                 : "=r"(b30), "=r"(b31) : "r"(a0 + 48 * 288));
                    mma_tf32(acc[0][0], A[kf], b00, b01);
                    mma_tf32(acc[0][1], A[kf], b10, b11);
                    mma_tf32(acc[1][0], A[kf], b20, b21);
                    mma_tf32(acc[1][1], A[kf], b30, b31);
                }
                // fused epilogue: tanh + W2 contraction into register att partials
                #pragma unroll
                for (int p = 0; p < 2; p++) {
                    #pragma unroll
                    for (int nf = 0; nf < 2; nf++) {
                        int q = npp * 4 + p * 2 + nf;
                        int col0 = half * 256 + q * 8 + 2 * t;
                        float4 wA = ((float4*)w2s)[col0];
                        float4 wB = ((float4*)w2s)[col0 + 1];
                        #pragma unroll
                        for (int rh = 0; rh < 2; rh++) {
                            float h0 = fast_tanh(acc[p][nf][rh * 2 + 0]);
                            float h1 = fast_tanh(acc[p][nf][rh * 2 + 1]);
                            att[rh][0] += h0 * wA.x + h1 * wB.x;
                            att[rh][1] += h0 * wA.y + h1 * wB.y;
                            att[rh][2] += h0 * wA.z + h1 * wB.z;
                            att[rh][3] += h0 * wA.w + h1 * wB.w;
                        }
                    }
                }
            }
        }
    }
    __syncthreads();

    // ---- Phase 3: reduce att over the 4-lane k-group, write atts ----
    if (wid < NWARP_C) {
        #pragma unroll
        for (int rh = 0; rh < 2; rh++)
            #pragma unroll
            for (int k = 0; k < 4; k++) {
                float v = att[rh][k];
                v += __shfl_xor_sync(0xffffffffu, v, 1);
                v += __shfl_xor_sync(0xffffffffu, v, 2);
                if (t == 0) {
                    int s = wid * 16 + rh * 8 + g;
                    if (s < S_DIM) atts[k * ATTP + s] = v;
                }
            }
    }
    __syncthreads();

    // ---- Phase 4: mask + softmax (one warp per head) ----
    if (tid < 32 * NH) {
        const int k = tid >> 5, l = tid & 31;
        const int* mrow = mask + (size_t)b * S_DIM;
        const float NEGV = -4294967296.0f;
        float mx = -INFINITY;
        for (int s = l; s < S_DIM; s += 32) {
            float v = atts[k * ATTP + s];
            if (mrow[s] == 0) v = NEGV;
            atts[k * ATTP + s] = v;
            mx = fmaxf(mx, v);
        }
        #pragma unroll
        for (int o = 16; o > 0; o >>= 1) mx = fmaxf(mx, __shfl_xor_sync(0xffffffffu, mx, o));
        float sum = 0.0f;
        for (int s = l; s < S_DIM; s += 32) {
            float e = expf(atts[k * ATTP + s] - mx);
            atts[k * ATTP + s] = e;
            sum += e;
        }
        #pragma unroll
        for (int o = 16; o > 0; o >>= 1) sum += __shfl_xor_sync(0xffffffffu, sum, o);
        float inv = 1.0f / sum;
        for (int s = l; s < S_DIM; s += 32) atts[k * ATTP + s] *= inv;
    }
    __syncthreads();

    // ---- Phase 5: interest[k][h] = sum_s att[k][s] * item[b][s][h], 4 s-slices ----
    {
        const int slice = tid >> 7, h = tid & 127;
        const float* ib = itemb + h;
        float a0 = 0.f, a1 = 0.f, a2 = 0.f, a3 = 0.f;
        const int s0 = slice * 50, s1 = s0 + 50;
        #pragma unroll 5
        for (int s = s0; s < s1; s++) {
            float xv = ib[(size_t)s * H_DIM];
            a0 += atts[0 * ATTP + s] * xv;
            a1 += atts[1 * ATTP + s] * xv;
            a2 += atts[2 * ATTP + s] * xv;
            a3 += atts[3 * ATTP + s] * xv;
        }
        if (slice > 0) {
            float* o = outb + (slice - 1) * 512;
            o[0 * 128 + h] = a0; o[1 * 128 + h] = a1;
            o[2 * 128 + h] = a2; o[3 * 128 + h] = a3;
        }
        __syncthreads();
        if (slice == 0) {
            float* ob = out + (size_t)b * (NH * H_DIM);
            #pragma unroll
            for (int k = 0; k < 4; k++) {
                float v = (k == 0 ? a0 : k == 1 ? a1 : k == 2 ? a2 : a3);
                v += outb[0 * 512 + k * 128 + h];
                v += outb[1 * 512 + k * 128 + h];
                v += outb[2 * 512 + k * 128 + h];
                ob[k * H_DIM + h] = v;
            }
        }
    }
}

extern "C" void kernel_launch(void* const* d_in, const int* in_sizes, int n_in,
                              void* d_out, int out_size)
{
    const float* item = (const float*)d_in[0];
    const int*   mask = (const int*)  d_in[1];
    const float* pos  = (const float*)d_in[2];
    const float* W1   = (const float*)d_in[3];
    const float* W2   = (const float*)d_in[4];
    float* out = (float*)d_out;

    const int B = in_sizes[0] / (S_DIM * H_DIM);

    cudaFuncSetAttribute(mha_mma_kernel,
                         cudaFuncAttributeMaxDynamicSharedMemorySize, SM_TOTAL);
    mha_mma_kernel<<<B, NT, SM_TOTAL>>>(item, mask, pos, W1, W2, out);
}

// round 6
// speedup vs baseline: 2.5764x; 1.0341x over previous
#include <cuda_runtime.h>
#include <math.h>
#include <stdint.h>

#define S_DIM 200
#define H_DIM 128
#define F_DIM 512
#define NH 4
#define ATTP 208
#define NT 512
#define MROWS 208
#define NWARP_C 13
#define BUFQ 65536            // one quarter fragment buffer (128 blocks * 512B)

// smem layout: [buf0 0..64K][buf1 64K..128K] (X pitch-132 region overlaps both,
// dead after A-hoist), then W2/att/outb.
#define SM_W2    131072
#define SM_ATT   (SM_W2 + 8192)
#define SM_OUTB  (SM_ATT + 3328)
#define SM_TOTAL (SM_OUTB + 6144)   // 148736 B

static __device__ __forceinline__ uint32_t smem_u32(const void* p) {
    uint32_t a;
    asm("{ .reg .u64 t; cvta.to.shared.u64 t, %1; cvt.u32.u64 %0, t; }" : "=r"(a) : "l"(p));
    return a;
}
static __device__ __forceinline__ uint32_t f2tf32(float x) {
    uint32_t r; asm("cvt.rna.tf32.f32 %0, %1;" : "=r"(r) : "f"(x)); return r;
}
static __device__ __forceinline__ float fast_tanh(float x) {
    float y = x * 2.8853900817779268f;   // 2*log2(e)
    float t; asm("ex2.approx.f32 %0, %1;" : "=f"(t) : "f"(y));
    float r; asm("rcp.approx.f32 %0, %1;" : "=f"(r) : "f"(t + 1.0f));
    return fmaf(-2.0f, r, 1.0f);
}
static __device__ __forceinline__ void mma_tf32(float* c, const uint32_t* a,
                                                uint32_t b0, uint32_t b1) {
    asm volatile(
        "mma.sync.aligned.m16n8k8.row.col.f32.tf32.tf32.f32 "
        "{%0,%1,%2,%3}, {%4,%5,%6,%7}, {%8,%9}, {%0,%1,%2,%3};"
        : "+f"(c[0]), "+f"(c[1]), "+f"(c[2]), "+f"(c[3])
        : "r"(a[0]), "r"(a[1]), "r"(a[2]), "r"(a[3]), "r"(b0), "r"(b1));
}

// ---- W1 staging: block blk = npair*16 + kf; lane (g,t) slot holds
// {W1[kf8+t][n0+g], W1[kf8+t+4][n0+g], W1[kf8+t][n0+8+g], W1[kf8+t+4][n0+8+g]} tf32
static __device__ __forceinline__ void stage_ldg(float* pv, int ioff, int qcol,
                                                 const float* __restrict__ W1,
                                                 int wid, int g, int t) {
    #pragma unroll
    for (int j = 0; j < 2; j++) {
        int blk = (ioff + j) * 16 + wid;
        int npair = blk >> 4, kf = blk & 15;
        const float* p = W1 + (size_t)(kf * 8 + t) * F_DIM + qcol + npair * 16 + g;
        pv[4 * j + 0] = p[0];
        pv[4 * j + 1] = p[4 * F_DIM];
        pv[4 * j + 2] = p[8];
        pv[4 * j + 3] = p[8 + 4 * F_DIM];
    }
}
static __device__ __forceinline__ void stage_sts(const float* pv, int ioff,
                                                 uint32_t bufb, int wid, int lane) {
    #pragma unroll
    for (int j = 0; j < 2; j++) {
        int blk = (ioff + j) * 16 + wid;
        uint32_t q0 = f2tf32(pv[4 * j + 0]), q1 = f2tf32(pv[4 * j + 1]);
        uint32_t q2 = f2tf32(pv[4 * j + 2]), q3 = f2tf32(pv[4 * j + 3]);
        asm volatile("st.shared.v4.b32 [%0], {%1,%2,%3,%4};"
                     :: "r"(bufb + (uint32_t)blk * 512 + (uint32_t)lane * 16),
                        "r"(q0), "r"(q1), "r"(q2), "r"(q3));
    }
}

static __device__ __forceinline__ void sweep_npp(uint32_t bq, int q, int npp,
                                                 const uint32_t (*A)[4],
                                                 float (*att)[4],
                                                 const float* __restrict__ w2s,
                                                 int lane, int t) {
    float acc[2][2][4];
    #pragma unroll
    for (int p = 0; p < 2; p++)
        #pragma unroll
        for (int nf = 0; nf < 2; nf++)
            #pragma unroll
            for (int i = 0; i < 4; i++) acc[p][nf][i] = 0.0f;

    uint32_t base = bq + (uint32_t)(npp * 32) * 512 + (uint32_t)lane * 16;
    #pragma unroll
    for (int kf = 0; kf < 16; kf++) {
        uint32_t x0, x1, x2, x3, y0, y1, y2, y3;
        uint32_t a0 = base + (uint32_t)kf * 512;
        asm volatile("ld.shared.v4.b32 {%0,%1,%2,%3}, [%4];"
                     : "=r"(x0), "=r"(x1), "=r"(x2), "=r"(x3) : "r"(a0));
        asm volatile("ld.shared.v4.b32 {%0,%1,%2,%3}, [%4];"
                     : "=r"(y0), "=r"(y1), "=r"(y2), "=r"(y3) : "r"(a0 + 8192));
        mma_tf32(acc[0][0], A[kf], x0, x1);
        mma_tf32(acc[0][1], A[kf], x2, x3);
        mma_tf32(acc[1][0], A[kf], y0, y1);
        mma_tf32(acc[1][1], A[kf], y2, y3);
    }
    // fused epilogue: tanh + W2 contraction
    #pragma unroll
    for (int p = 0; p < 2; p++) {
        #pragma unroll
        for (int nf = 0; nf < 2; nf++) {
            int nf4 = q * 128 + (npp * 2 + p) * 16 + nf * 8 + 2 * t;
            float4 wA = ((const float4*)w2s)[nf4];
            float4 wB = ((const float4*)w2s)[nf4 + 1];
            #pragma unroll
            for (int rh = 0; rh < 2; rh++) {
                float h0 = fast_tanh(acc[p][nf][rh * 2 + 0]);
                float h1 = fast_tanh(acc[p][nf][rh * 2 + 1]);
                att[rh][0] += h0 * wA.x + h1 * wB.x;
                att[rh][1] += h0 * wA.y + h1 * wB.y;
                att[rh][2] += h0 * wA.z + h1 * wB.z;
                att[rh][3] += h0 * wA.w + h1 * wB.w;
            }
        }
    }
}

__global__ __launch_bounds__(NT, 1)
void mha_mma_kernel(const float* __restrict__ item,
                    const int*   __restrict__ mask,
                    const float* __restrict__ pos,
                    const float* __restrict__ W1,
                    const float* __restrict__ W2,
                    float* __restrict__ out)
{
    extern __shared__ char smem[];
    const uint32_t smb = smem_u32(smem);
    uint32_t* xw32 = (uint32_t*)smem;            // X pitch-132, dead after A-hoist
    float*    w2s  = (float*)(smem + SM_W2);
    float*    atts = (float*)(smem + SM_ATT);
    float*    outb = (float*)(smem + SM_OUTB);

    const int tid = threadIdx.x, wid = tid >> 5, lane = tid & 31;
    const int g = lane >> 2, t = lane & 3;
    const int b = blockIdx.x;
    const float* itemb = item + (size_t)b * (S_DIM * H_DIM);

    // ---- Phase 0: X+pos -> smem (tf32), pitch 132. W2 copy. ----
    for (int idx = tid; idx < MROWS * 128; idx += NT) {
        int row = idx >> 7, h = idx & 127;
        float v = 0.0f;
        if (row < S_DIM) v = itemb[row * 128 + h] + pos[row * 128 + h];
        xw32[row * 132 + h] = f2tf32(v);
    }
    if (tid < F_DIM) ((float4*)w2s)[tid] = ((const float4*)W2)[tid];
    __syncthreads();

    // ---- Phase 1: prefetch q0 chunk0 (global), hoist A fragments from X ----
    float pv[8];
    stage_ldg(pv, 0, 0, W1, wid, g, t);

    uint32_t A[16][4];
    if (wid < NWARP_C) {
        int r0 = wid * 16 + g;
        #pragma unroll
        for (int kf = 0; kf < 16; kf++) {
            int c0 = kf * 8 + t;
            A[kf][0] = xw32[r0 * 132 + c0];
            A[kf][1] = xw32[(r0 + 8) * 132 + c0];
            A[kf][2] = xw32[r0 * 132 + c0 + 4];
            A[kf][3] = xw32[(r0 + 8) * 132 + c0 + 4];
        }
    }
    __syncthreads();   // all A-hoists done before buf0 overwrites X

    // stage remainder of quarter 0 into buf0
    stage_sts(pv, 0, smb, wid, lane);
    stage_ldg(pv, 2, 0, W1, wid, g, t); stage_sts(pv, 2, smb, wid, lane);
    stage_ldg(pv, 4, 0, W1, wid, g, t); stage_sts(pv, 4, smb, wid, lane);
    stage_ldg(pv, 6, 0, W1, wid, g, t); stage_sts(pv, 6, smb, wid, lane);
    __syncthreads();

    float att[2][4];
    #pragma unroll
    for (int rh = 0; rh < 2; rh++)
        #pragma unroll
        for (int k = 0; k < 4; k++) att[rh][k] = 0.0f;

    // ---- Phase 2: 4 quarters, double-buffered, staging pipelined with sweeps ----
    #pragma unroll 1
    for (int q = 0; q < 4; q++) {
        const uint32_t bq = smb + (uint32_t)(q & 1) * BUFQ;
        const uint32_t bn = smb + (uint32_t)((q + 1) & 1) * BUFQ;
        const int qc = (q + 1) * 128;
        const bool pre = (q < 3);

        if (pre) stage_ldg(pv, 0, qc, W1, wid, g, t);
        if (wid < NWARP_C) sweep_npp(bq, q, 0, A, att, w2s, lane, t);
        if (pre) { stage_sts(pv, 0, bn, wid, lane); stage_ldg(pv, 2, qc, W1, wid, g, t); }
        if (wid < NWARP_C) sweep_npp(bq, q, 1, A, att, w2s, lane, t);
        if (pre) { stage_sts(pv, 2, bn, wid, lane); stage_ldg(pv, 4, qc, W1, wid, g, t); }
        if (wid < NWARP_C) sweep_npp(bq, q, 2, A, att, w2s, lane, t);
        if (pre) { stage_sts(pv, 4, bn, wid, lane); stage_ldg(pv, 6, qc, W1, wid, g, t); }
        if (wid < NWARP_C) sweep_npp(bq, q, 3, A, att, w2s, lane, t);
        if (pre) stage_sts(pv, 6, bn, wid, lane);
        __syncthreads();
    }

    // ---- Phase 3: reduce att over the 4-lane k-group, write atts ----
    if (wid < NWARP_C) {
        #pragma unroll
        for (int rh = 0; rh < 2; rh++)
            #pragma unroll
            for (int k = 0; k < 4; k++) {
                float v = att[rh][k];
                v += __shfl_xor_sync(0xffffffffu, v, 1);
                v += __shfl_xor_sync(0xffffffffu, v, 2);
                if (t == 0) {
                    int s = wid * 16 + rh * 8 + g;
                    if (s < S_DIM) atts[k * ATTP + s] = v;
                }
            }
    }
    __syncthreads();

    // ---- Phase 4: mask + softmax (one warp per head) ----
    if (tid < 32 * NH) {
        const int k = tid >> 5, l = tid & 31;
        const int* mrow = mask + (size_t)b * S_DIM;
        const float NEGV = -4294967296.0f;
        float mx = -INFINITY;
        for (int s = l; s < S_DIM; s += 32) {
            float v = atts[k * ATTP + s];
            if (mrow[s] == 0) v = NEGV;
            atts[k * ATTP + s] = v;
            mx = fmaxf(mx, v);
        }
        #pragma unroll
        for (int o = 16; o > 0; o >>= 1) mx = fmaxf(mx, __shfl_xor_sync(0xffffffffu, mx, o));
        float sum = 0.0f;
        for (int s = l; s < S_DIM; s += 32) {
            float e = expf(atts[k * ATTP + s] - mx);
            atts[k * ATTP + s] = e;
            sum += e;
        }
        #pragma unroll
        for (int o = 16; o > 0; o >>= 1) sum += __shfl_xor_sync(0xffffffffu, sum, o);
        float inv = 1.0f / sum;
        for (int s = l; s < S_DIM; s += 32) atts[k * ATTP + s] *= inv;
    }
    __syncthreads();

    // ---- Phase 5: interest[k][h] = sum_s att[k][s] * item[b][s][h], 4 s-slices ----
    {
        const int slice = tid >> 7, h = tid & 127;
        const float* ib = itemb + h;
        float a0 = 0.f, a1 = 0.f, a2 = 0.f, a3 = 0.f;
        const int s0 = slice * 50, s1 = s0 + 50;
        #pragma unroll 5
        for (int s = s0; s < s1; s++) {
            float xv = ib[(size_t)s * H_DIM];
            a0 += atts[0 * ATTP + s] * xv;
            a1 += atts[1 * ATTP + s] * xv;
            a2 += atts[2 * ATTP + s] * xv;
            a3 += atts[3 * ATTP + s] * xv;
        }
        if (slice > 0) {
            float* o = outb + (slice - 1) * 512;
            o[0 * 128 + h] = a0; o[1 * 128 + h] = a1;
            o[2 * 128 + h] = a2; o[3 * 128 + h] = a3;
        }
        __syncthreads();
        if (slice == 0) {
            float* ob = out + (size_t)b * (NH * H_DIM);
            #pragma unroll
            for (int k = 0; k < 4; k++) {
                float v = (k == 0 ? a0 : k == 1 ? a1 : k == 2 ? a2 : a3);
                v += outb[0 * 512 + k * 128 + h];
                v += outb[1 * 512 + k * 128 + h];
                v += outb[2 * 512 + k * 128 + h];
                ob[k * H_DIM + h] = v;
            }
        }
    }
}

extern "C" void kernel_launch(void* const* d_in, const int* in_sizes, int n_in,
                              void* d_out, int out_size)
{
    const float* item = (const float*)d_in[0];
    const int*   mask = (const int*)  d_in[1];
    const float* pos  = (const float*)d_in[2];
    const float* W1   = (const float*)d_in[3];
    const float* W2   = (const float*)d_in[4];
    float* out = (float*)d_out;

    const int B = in_sizes[0] / (S_DIM * H_DIM);

    cudaFuncSetAttribute(mha_mma_kernel,
                         cudaFuncAttributeMaxDynamicSharedMemorySize, SM_TOTAL);
    mha_mma_kernel<<<B, NT, SM_TOTAL>>>(item, mask, pos, W1, W2, out);
}